// round 7
// baseline (speedup 1.0000x reference)
#include <cuda_runtime.h>
#include <cuda_fp16.h>

#define N_NODES 10000
#define NB 32
#define NF 66
#define NU 64
#define NU2 128
#define SROW 2048            // halves per node state-row
#define SROWQ 256            // uint4 per state-row
#define NNZ_MAX 330000
#define XS_ELEMS (N_NODES * SROW)
#define S_STRIDE 640000      // N*NU per batch
#define NCH 10               // pipeline chunks (1000 nodes each)
#define NODES_PER_CH (N_NODES / NCH)

typedef unsigned long long ull;

__device__ __half  g_XSh[XS_ELEMS];        // gather source pass 1 (state fp16) — read-only after build
__device__ __half  g_XS2h[XS_ELEMS];       // gather source pass 2 (r*state fp16)
__device__ __half  g_X1h[XS_ELEMS];        // spmm pass-1 output (read by GEMM1)
__device__ __half  g_X2h[XS_ELEMS];        // spmm pass-2 output (read by GEMM2)
__device__ float2  g_XI[N_NODES * NB];     // inputs-part gather source
__device__ float2  g_YI[N_NODES * NB];     // inputs-part spmm result (reused)
__device__ __half  g_Uh[NB * S_STRIDE];    // update gate
__device__ int     g_cnt[N_NODES];
__device__ int     g_cur[N_NODES];
__device__ int     g_rowptr[N_NODES + 1];
__device__ int     g_col[NNZ_MAX];
__device__ float   g_val[NNZ_MAX];

// ---------- streams/events (created at static init; no device memory) ----------
static cudaStream_t g_s1;
static cudaEvent_t  g_evFork, g_evBuild, g_evCsr, g_evG1r, g_evDone;
static cudaEvent_t  g_evS1[NCH], g_evS2[NCH];
namespace {
struct HxInit {
    HxInit() {
        cudaStreamCreateWithFlags(&g_s1, cudaStreamNonBlocking);
        cudaEventCreateWithFlags(&g_evFork,  cudaEventDisableTiming);
        cudaEventCreateWithFlags(&g_evBuild, cudaEventDisableTiming);
        cudaEventCreateWithFlags(&g_evCsr,   cudaEventDisableTiming);
        cudaEventCreateWithFlags(&g_evG1r,   cudaEventDisableTiming);
        cudaEventCreateWithFlags(&g_evDone,  cudaEventDisableTiming);
        for (int i = 0; i < NCH; i++) {
            cudaEventCreateWithFlags(&g_evS1[i], cudaEventDisableTiming);
            cudaEventCreateWithFlags(&g_evS2[i], cudaEventDisableTiming);
        }
    }
};
static HxInit g_hxinit;
}

// ---------- f32x2 helpers ----------
__device__ __forceinline__ ull pk2(float lo, float hi) {
    ull r; asm("mov.b64 %0, {%1, %2};" : "=l"(r) : "f"(lo), "f"(hi)); return r;
}
__device__ __forceinline__ void upk2(ull v, float& lo, float& hi) {
    asm("mov.b64 {%0, %1}, %2;" : "=f"(lo), "=f"(hi) : "l"(v));
}
__device__ __forceinline__ void fma2(ull& d, ull a, ull b) {
    asm("fma.rn.f32x2 %0, %1, %2, %0;" : "+l"(d) : "l"(a), "l"(b));
}
__device__ __forceinline__ float sigf(float x) { return 1.0f / (1.0f + __expf(-x)); }

// ---------------- CSR build ----------------
__global__ void k_zero() {
    int i = blockIdx.x * blockDim.x + threadIdx.x;
    if (i < N_NODES) { g_cnt[i] = 0; g_cur[i] = 0; }
}
__global__ void k_hist(const int* __restrict__ rows, int nnz) {
    int i = blockIdx.x * blockDim.x + threadIdx.x;
    if (i < nnz) atomicAdd(&g_cnt[rows[i]], 1);
}
__global__ void k_scan() {
    __shared__ int s[1024];
    int tid = threadIdx.x;
    int loc[10];
    int sum = 0;
#pragma unroll
    for (int k = 0; k < 10; k++) {
        int i = tid * 10 + k;
        int v = (i < N_NODES) ? g_cnt[i] : 0;
        loc[k] = v; sum += v;
    }
    s[tid] = sum;
    __syncthreads();
    for (int d = 1; d < 1024; d <<= 1) {
        int v = (tid >= d) ? s[tid - d] : 0;
        __syncthreads();
        s[tid] += v;
        __syncthreads();
    }
    int run = s[tid] - sum;
#pragma unroll
    for (int k = 0; k < 10; k++) {
        int i = tid * 10 + k;
        if (i < N_NODES) g_rowptr[i] = run;
        run += loc[k];
    }
    if (tid == 1023) g_rowptr[N_NODES] = run;
}
__global__ void k_scatter(const int* __restrict__ rows, const int* __restrict__ cols,
                          const float* __restrict__ vals, int nnz) {
    int i = blockIdx.x * blockDim.x + threadIdx.x;
    if (i < nnz) {
        int r = rows[i];
        int p = g_rowptr[r] + atomicAdd(&g_cur[r], 1);
        g_col[p] = cols[i];
        g_val[p] = vals[i];
    }
}

// ---------------- fused builder (XS fp16 + XI) ----------------
#define XS_Q (XS_ELEMS / 8)
__global__ void k_build(const float* __restrict__ inputs, const float* __restrict__ state) {
    int id = blockIdx.x * 256 + threadIdx.x;
    if (id < XS_Q) {
        int i8 = id * 8;
        int n = i8 >> 11;
        int b = (i8 >> 6) & 31;
        int u = i8 & 63;
        const float* sp = state + (size_t)b * S_STRIDE + n * 64 + u;
        float4 s0 = *(const float4*)sp;
        float4 s1 = *(const float4*)(sp + 4);
        uint4 o;
        ((__half2*)&o)[0] = __floats2half2_rn(s0.x, s0.y);
        ((__half2*)&o)[1] = __floats2half2_rn(s0.z, s0.w);
        ((__half2*)&o)[2] = __floats2half2_rn(s1.x, s1.y);
        ((__half2*)&o)[3] = __floats2half2_rn(s1.z, s1.w);
        ((uint4*)g_XSh)[id] = o;
    } else {
        int j = id - XS_Q;
        if (j < N_NODES * NB) {
            int b = j / N_NODES, n = j - b * N_NODES;
            float2 v = *(const float2*)&inputs[b * 20000 + 2 * n];
            g_XI[n * 32 + b] = v;
        }
    }
}

// ---------------- SpMM (inputs part, once) ----------------
__global__ void k_spmm_in() {
    int gw = (blockIdx.x * 256 + threadIdx.x) >> 5;
    int lane = threadIdx.x & 31;
    if (gw >= N_NODES) return;
    int beg = __ldg(&g_rowptr[gw]), end = __ldg(&g_rowptr[gw + 1]);
    float2 acc = make_float2(0.f, 0.f);
    for (int e = beg; e < end; e++) {
        int c = __ldg(&g_col[e]);
        float v = __ldg(&g_val[e]);
        float2 x = g_XI[c * 32 + lane];
        acc.x = fmaf(v, x.x, acc.x);
        acc.y = fmaf(v, x.y, acc.y);
    }
    g_YI[gw * 32 + lane] = acc;
}

// ---------------- SpMM (state part): 2 blocks/row, 128 threads ----------------
// PASS selects buffers INSIDE device code — __device__ globals must never be
// passed as kernel arguments from host (host shadow address + GB300 ATS
// silently reads host zeros; that was the round-5/6 corruption).
__device__ __forceinline__ void acc8(float* a, uint4 q, float v) {
    float2 f0 = __half22float2(*(__half2*)&q.x);
    float2 f1 = __half22float2(*(__half2*)&q.y);
    float2 f2 = __half22float2(*(__half2*)&q.z);
    float2 f3 = __half22float2(*(__half2*)&q.w);
    a[0] = fmaf(v, f0.x, a[0]); a[1] = fmaf(v, f0.y, a[1]);
    a[2] = fmaf(v, f1.x, a[2]); a[3] = fmaf(v, f1.y, a[3]);
    a[4] = fmaf(v, f2.x, a[4]); a[5] = fmaf(v, f2.y, a[5]);
    a[6] = fmaf(v, f3.x, a[6]); a[7] = fmaf(v, f3.y, a[7]);
}

template <int PASS>
__global__ void __launch_bounds__(128, 10) k_spmm_s(int node_base) {
    const uint4* __restrict__ X = (const uint4*)(PASS == 0 ? g_XSh : g_XS2h);
    uint4* __restrict__ Y = (uint4*)(PASS == 0 ? g_X1h : g_X2h);
    int n = node_base + (blockIdx.x >> 1);
    int slot = ((blockIdx.x & 1) << 7) + threadIdx.x;   // uint4 index within row
    int t = threadIdx.x;
    __shared__ int   scol[128];
    __shared__ float sval[128];
    float a[8] = {0.f, 0.f, 0.f, 0.f, 0.f, 0.f, 0.f, 0.f};
    int beg = __ldg(&g_rowptr[n]), end = __ldg(&g_rowptr[n + 1]);
    for (int base = beg; base < end; base += 128) {
        int cnt = min(128, end - base);
        __syncthreads();
        if (t < cnt) { scol[t] = g_col[base + t]; sval[t] = g_val[base + t]; }
        __syncthreads();
        int e = 0;
        for (; e + 4 <= cnt; e += 4) {
            uint4 q0 = X[(size_t)scol[e + 0] * SROWQ + slot];
            uint4 q1 = X[(size_t)scol[e + 1] * SROWQ + slot];
            uint4 q2 = X[(size_t)scol[e + 2] * SROWQ + slot];
            uint4 q3 = X[(size_t)scol[e + 3] * SROWQ + slot];
            acc8(a, q0, sval[e + 0]);
            acc8(a, q1, sval[e + 1]);
            acc8(a, q2, sval[e + 2]);
            acc8(a, q3, sval[e + 3]);
        }
        for (; e < cnt; e++) {
            uint4 q = X[(size_t)scol[e] * SROWQ + slot];
            acc8(a, q, sval[e]);
        }
    }
    uint4 o;
    ((__half2*)&o)[0] = __floats2half2_rn(a[0], a[1]);
    ((__half2*)&o)[1] = __floats2half2_rn(a[2], a[3]);
    ((__half2*)&o)[2] = __floats2half2_rn(a[4], a[5]);
    ((__half2*)&o)[3] = __floats2half2_rn(a[6], a[7]);
    Y[(size_t)n * SROWQ + slot] = o;
}

// ---------------- shared xs fill (conflict-free, padded stride 66) ----------------
// X1src is always a DEVICE-context reference to a __device__ global (legal).
__device__ __forceinline__ void fill_xs(float xs[NF][66], int tid, int B0,
                                        const __half* __restrict__ X1src) {
    const uint2* src = (const uint2*)(X1src + (size_t)B0 * 4096);
#pragma unroll
    for (int k = 0; k < 8; k++) {
        int idx4 = tid + k * 128;        // 1024 uint2 = 64 rows x 16
        int r = idx4 >> 4;
        int u = (idx4 & 15) * 4;
        uint2 q = src[idx4];
        float2 f0 = __half22float2(*(__half2*)&q.x);
        float2 f1 = __half22float2(*(__half2*)&q.y);
        xs[u + 2][r] = f0.x; xs[u + 3][r] = f0.y;
        xs[u + 4][r] = f1.x; xs[u + 5][r] = f1.y;
    }
    {
        int r = tid >> 1, f = tid & 1;
        int node = 2 * B0 + (r >> 5), b = r & 31;
        float2 y = g_YI[node * 32 + b];
        xs[f][r] = f ? y.y : y.x;
    }
}

// ---------------- GEMM1 fused: sigmoid; r*state -> g_XS2h, u -> g_Uh ----------------
__global__ void __launch_bounds__(128) k_gemm1f(const float* __restrict__ w,
                                                const float* __restrict__ bias,
                                                int b0_base) {
    __shared__ float xs[NF][66];
    __shared__ float ws[NF * NU2];
    int tid = threadIdx.x;
    int B0 = b0_base + blockIdx.x;       // nodes 2B0, 2B0+1
    for (int i = tid; i < NF * NU2; i += 128) ws[i] = w[i];
    fill_xs(xs, tid, B0, g_X1h);
    __syncthreads();
    int tx = tid & 15, ty = tid >> 4;
    ull acc[4][8];
#pragma unroll
    for (int i = 0; i < 4; i++)
#pragma unroll
        for (int j = 0; j < 8; j++) acc[i][j] = 0ull;

#pragma unroll 2
    for (int f = 0; f < NF; f++) {
        ull a[4];
#pragma unroll
        for (int rp = 0; rp < 4; rp++)
            a[rp] = *(const ull*)&xs[f][ty * 8 + rp * 2];
        float4 w0 = *(const float4*)&ws[f * NU2 + tx * 8];
        float4 w1 = *(const float4*)&ws[f * NU2 + tx * 8 + 4];
        ull wd[8];
        wd[0] = pk2(w0.x, w0.x); wd[1] = pk2(w0.y, w0.y);
        wd[2] = pk2(w0.z, w0.z); wd[3] = pk2(w0.w, w0.w);
        wd[4] = pk2(w1.x, w1.x); wd[5] = pk2(w1.y, w1.y);
        wd[6] = pk2(w1.z, w1.z); wd[7] = pk2(w1.w, w1.w);
#pragma unroll
        for (int rp = 0; rp < 4; rp++)
#pragma unroll
            for (int j = 0; j < 8; j++) fma2(acc[rp][j], a[rp], wd[j]);
    }

    float bz[8];
    {
        float4 bb0 = *(const float4*)&bias[tx * 8];
        float4 bb1 = *(const float4*)&bias[tx * 8 + 4];
        bz[0] = bb0.x; bz[1] = bb0.y; bz[2] = bb0.z; bz[3] = bb0.w;
        bz[4] = bb1.x; bz[5] = bb1.y; bz[6] = bb1.z; bz[7] = bb1.w;
    }
    bool rside = (B0 < 2500);
#pragma unroll
    for (int rp = 0; rp < 4; rp++) {
#pragma unroll
        for (int h = 0; h < 2; h++) {
            int r = ty * 8 + rp * 2 + h;
            int nn = 2 * B0 + (r >> 5);
            int b = r & 31;
            float v[8];
#pragma unroll
            for (int j = 0; j < 8; j++) {
                float lo, hi; upk2(acc[rp][j], lo, hi);
                v[j] = sigf((h ? hi : lo) + bz[j]);
            }
            if (rside) {
                int t = 2 * nn + (tx >> 3);
                int c = (tx & 7) * 8;
                size_t off = (size_t)t * SROW + b * 64 + c;
                uint4 sh = *(const uint4*)&g_XSh[off];     // fp16 state (read-only buffer)
                float2 s0 = __half22float2(((__half2*)&sh)[0]);
                float2 s1 = __half22float2(((__half2*)&sh)[1]);
                float2 s2 = __half22float2(((__half2*)&sh)[2]);
                float2 s3 = __half22float2(((__half2*)&sh)[3]);
                uint4 o;
                ((__half2*)&o)[0] = __floats2half2_rn(v[0] * s0.x, v[1] * s0.y);
                ((__half2*)&o)[1] = __floats2half2_rn(v[2] * s1.x, v[3] * s1.y);
                ((__half2*)&o)[2] = __floats2half2_rn(v[4] * s2.x, v[5] * s2.y);
                ((__half2*)&o)[3] = __floats2half2_rn(v[6] * s3.x, v[7] * s3.y);
                *(uint4*)&g_XS2h[off] = o;                 // double buffer for pass 2
            } else {
                uint4 o;
                ((__half2*)&o)[0] = __floats2half2_rn(v[0], v[1]);
                ((__half2*)&o)[1] = __floats2half2_rn(v[2], v[3]);
                ((__half2*)&o)[2] = __floats2half2_rn(v[4], v[5]);
                ((__half2*)&o)[3] = __floats2half2_rn(v[6], v[7]);
                __stcs((uint4*)&g_Uh[(size_t)b * S_STRIDE + (nn - 5000) * 128 + tx * 8], o);
            }
        }
    }
}

// ---------------- GEMM2 + GRU combine ----------------
__global__ void __launch_bounds__(128) k_gemm2(const float* __restrict__ w,
                                               const float* __restrict__ bias,
                                               const float* __restrict__ state,
                                               float* __restrict__ out,
                                               int b0_base) {
    __shared__ float xs[NF][66];
    __shared__ float ws[NF * NU];
    int tid = threadIdx.x;
    int B0 = b0_base + blockIdx.x;
    for (int i = tid; i < NF * NU; i += 128) ws[i] = w[i];
    fill_xs(xs, tid, B0, g_X2h);
    __syncthreads();
    int tx = tid & 15, ty = tid >> 4;
    ull acc[4][4];
#pragma unroll
    for (int i = 0; i < 4; i++)
#pragma unroll
        for (int j = 0; j < 4; j++) acc[i][j] = 0ull;

#pragma unroll 2
    for (int f = 0; f < NF; f++) {
        ull a[4];
#pragma unroll
        for (int rp = 0; rp < 4; rp++)
            a[rp] = *(const ull*)&xs[f][ty * 8 + rp * 2];
        float4 w4 = *(const float4*)&ws[f * NU + tx * 4];
        ull wd[4];
        wd[0] = pk2(w4.x, w4.x); wd[1] = pk2(w4.y, w4.y);
        wd[2] = pk2(w4.z, w4.z); wd[3] = pk2(w4.w, w4.w);
#pragma unroll
        for (int rp = 0; rp < 4; rp++)
#pragma unroll
            for (int j = 0; j < 4; j++) fma2(acc[rp][j], a[rp], wd[j]);
    }

    float4 bb = *(const float4*)&bias[tx * 4];
    float bz[4] = {bb.x, bb.y, bb.z, bb.w};
#pragma unroll
    for (int rp = 0; rp < 4; rp++) {
#pragma unroll
        for (int h = 0; h < 2; h++) {
            int r = ty * 8 + rp * 2 + h;
            int n = 2 * B0 + (r >> 5), b = r & 31;
            size_t j = (size_t)b * S_STRIDE + n * 64 + tx * 4;
            float c[4];
#pragma unroll
            for (int q = 0; q < 4; q++) {
                float lo, hi; upk2(acc[rp][q], lo, hi);
                c[q] = fmaxf((h ? hi : lo) + bz[q], 0.0f);
            }
            uint2 uh = __ldcs((const uint2*)&g_Uh[j]);
            float2 u0 = __half22float2(*(__half2*)&uh.x);
            float2 u1 = __half22float2(*(__half2*)&uh.y);
            float4 s4 = *(const float4*)&state[j];
            float4 o;
            o.x = u0.x * s4.x + (1.0f - u0.x) * c[0];
            o.y = u0.y * s4.y + (1.0f - u0.y) * c[1];
            o.z = u1.x * s4.z + (1.0f - u1.x) * c[2];
            o.w = u1.y * s4.w + (1.0f - u1.y) * c[3];
            *(float4*)&out[j] = o;
        }
    }
}

// ---------------- launch: chunked pipeline across two streams ----------------
extern "C" void kernel_launch(void* const* d_in, const int* in_sizes, int n_in,
                              void* d_out, int out_size) {
    const float* inputs = (const float*)d_in[0];
    const float* state  = (const float*)d_in[1];
    const int*   m_rows = (const int*)d_in[2];
    const int*   m_cols = (const int*)d_in[3];
    const float* m_vals = (const float*)d_in[4];
    const float* w1     = (const float*)d_in[5];
    const float* b1     = (const float*)d_in[6];
    const float* w2     = (const float*)d_in[7];
    const float* b2     = (const float*)d_in[8];
    float* out = (float*)d_out;
    int nnz = in_sizes[2];

    // fork: builder on side stream, CSR chain on main
    cudaEventRecord(g_evFork, 0);
    cudaStreamWaitEvent(g_s1, g_evFork, 0);
    k_build<<<(XS_Q + N_NODES * NB + 255) / 256, 256, 0, g_s1>>>(inputs, state);
    cudaEventRecord(g_evBuild, g_s1);

    k_zero<<<(N_NODES + 255) / 256, 256>>>();
    k_hist<<<(nnz + 255) / 256, 256>>>(m_rows, nnz);
    k_scan<<<1, 1024>>>();
    k_scatter<<<(nnz + 255) / 256, 256>>>(m_rows, m_cols, m_vals, nnz);
    cudaEventRecord(g_evCsr, 0);

    // side: inputs-part SpMM (needs CSR; build already ordered on g_s1)
    cudaStreamWaitEvent(g_s1, g_evCsr, 0);
    k_spmm_in<<<(N_NODES * 32 + 255) / 256, 256, 0, g_s1>>>();

    // main: SpMM1 chunks (needs build + CSR)
    cudaStreamWaitEvent(0, g_evBuild, 0);
    for (int c = 0; c < NCH; c++) {
        k_spmm_s<0><<<2 * NODES_PER_CH, 128>>>(c * NODES_PER_CH);
        cudaEventRecord(g_evS1[c], 0);
    }

    // side: GEMM1 chunks, each behind its SpMM1 chunk (r-side chunks 0..4 first)
    for (int c = 0; c < NCH; c++) {
        cudaStreamWaitEvent(g_s1, g_evS1[c], 0);
        k_gemm1f<<<NODES_PER_CH / 2, 128, 0, g_s1>>>(w1, b1, c * NODES_PER_CH / 2);
        if (c == NCH / 2 - 1) cudaEventRecord(g_evG1r, g_s1);   // r-side complete
    }

    // main: SpMM2 chunks (needs all r-side GEMM1 -> g_XS2h complete);
    // writes g_X2h, so no conflict with u-side GEMM1 reads of g_X1h
    cudaStreamWaitEvent(0, g_evG1r, 0);
    for (int c = 0; c < NCH; c++) {
        k_spmm_s<1><<<2 * NODES_PER_CH, 128>>>(c * NODES_PER_CH);
        cudaEventRecord(g_evS2[c], 0);
    }

    // side: GEMM2 chunks behind their SpMM2 chunks (after GEMM1 on g_s1 in-order)
    for (int c = 0; c < NCH; c++) {
        cudaStreamWaitEvent(g_s1, g_evS2[c], 0);
        k_gemm2<<<NODES_PER_CH / 2, 128, 0, g_s1>>>(w2, b2, state, out, c * NODES_PER_CH / 2);
    }
    cudaEventRecord(g_evDone, g_s1);
    cudaStreamWaitEvent(0, g_evDone, 0);   // join back to capture origin stream
}

// round 8
// speedup vs baseline: 1.1370x; 1.1370x over previous
#include <cuda_runtime.h>
#include <cuda_fp16.h>

#define N_NODES 10000
#define NB 32
#define NF 66
#define NU 64
#define NU2 128
#define SROW 2048            // halves per node state-row
#define SROWQ 256            // uint4 per state-row
#define NNZ_MAX 330000
#define XS_ELEMS (N_NODES * SROW)
#define S_STRIDE 640000      // N*NU per batch
#define HALF_NODES 5000

typedef unsigned long long ull;

__device__ __half  g_XSh[XS_ELEMS];        // gather source pass 1 (state fp16) — read-only after build
__device__ __half  g_XS2h[XS_ELEMS];       // gather source pass 2 (r*state fp16)
__device__ __half  g_X1h[XS_ELEMS];        // spmm pass-1 output (read by GEMM1)
__device__ __half  g_X2h[XS_ELEMS];        // spmm pass-2 output (read by GEMM2)
__device__ float2  g_XI[N_NODES * NB];     // inputs-part gather source
__device__ float2  g_YI[N_NODES * NB];     // inputs-part spmm result (reused)
__device__ __half  g_Uh[NB * S_STRIDE];    // update gate
__device__ int     g_cnt[N_NODES];
__device__ int     g_cur[N_NODES];
__device__ int     g_rowptr[N_NODES + 1];
__device__ int     g_col[NNZ_MAX];
__device__ float   g_val[NNZ_MAX];

// ---------- streams/events (created at static init; no device memory) ----------
static cudaStream_t g_s1;
static cudaEvent_t  g_evFork, g_evBuild, g_evCsr, g_evG1r, g_evDone;
static cudaEvent_t  g_evS1[2], g_evS2[2];
namespace {
struct HxInit {
    HxInit() {
        cudaStreamCreateWithFlags(&g_s1, cudaStreamNonBlocking);
        cudaEventCreateWithFlags(&g_evFork,  cudaEventDisableTiming);
        cudaEventCreateWithFlags(&g_evBuild, cudaEventDisableTiming);
        cudaEventCreateWithFlags(&g_evCsr,   cudaEventDisableTiming);
        cudaEventCreateWithFlags(&g_evG1r,   cudaEventDisableTiming);
        cudaEventCreateWithFlags(&g_evDone,  cudaEventDisableTiming);
        for (int i = 0; i < 2; i++) {
            cudaEventCreateWithFlags(&g_evS1[i], cudaEventDisableTiming);
            cudaEventCreateWithFlags(&g_evS2[i], cudaEventDisableTiming);
        }
    }
};
static HxInit g_hxinit;
}

// ---------- f32x2 helpers ----------
__device__ __forceinline__ ull pk2(float lo, float hi) {
    ull r; asm("mov.b64 %0, {%1, %2};" : "=l"(r) : "f"(lo), "f"(hi)); return r;
}
__device__ __forceinline__ void upk2(ull v, float& lo, float& hi) {
    asm("mov.b64 {%0, %1}, %2;" : "=f"(lo), "=f"(hi) : "l"(v));
}
__device__ __forceinline__ void fma2(ull& d, ull a, ull b) {
    asm("fma.rn.f32x2 %0, %1, %2, %0;" : "+l"(d) : "l"(a), "l"(b));
}
__device__ __forceinline__ float sigf(float x) { return 1.0f / (1.0f + __expf(-x)); }

// ---------------- CSR build ----------------
__global__ void k_zero() {
    int i = blockIdx.x * blockDim.x + threadIdx.x;
    if (i < N_NODES) { g_cnt[i] = 0; g_cur[i] = 0; }
}
__global__ void k_hist(const int* __restrict__ rows, int nnz) {
    int i = blockIdx.x * blockDim.x + threadIdx.x;
    if (i < nnz) atomicAdd(&g_cnt[rows[i]], 1);
}
__global__ void k_scan() {
    __shared__ int s[1024];
    int tid = threadIdx.x;
    int loc[10];
    int sum = 0;
#pragma unroll
    for (int k = 0; k < 10; k++) {
        int i = tid * 10 + k;
        int v = (i < N_NODES) ? g_cnt[i] : 0;
        loc[k] = v; sum += v;
    }
    s[tid] = sum;
    __syncthreads();
    for (int d = 1; d < 1024; d <<= 1) {
        int v = (tid >= d) ? s[tid - d] : 0;
        __syncthreads();
        s[tid] += v;
        __syncthreads();
    }
    int run = s[tid] - sum;
#pragma unroll
    for (int k = 0; k < 10; k++) {
        int i = tid * 10 + k;
        if (i < N_NODES) g_rowptr[i] = run;
        run += loc[k];
    }
    if (tid == 1023) g_rowptr[N_NODES] = run;
}
__global__ void k_scatter(const int* __restrict__ rows, const int* __restrict__ cols,
                          const float* __restrict__ vals, int nnz) {
    int i = blockIdx.x * blockDim.x + threadIdx.x;
    if (i < nnz) {
        int r = rows[i];
        int p = g_rowptr[r] + atomicAdd(&g_cur[r], 1);
        g_col[p] = cols[i];
        g_val[p] = vals[i];
    }
}

// ---------------- fused builder (XS fp16 + XI) ----------------
#define XS_Q (XS_ELEMS / 8)
__global__ void k_build(const float* __restrict__ inputs, const float* __restrict__ state) {
    int id = blockIdx.x * 256 + threadIdx.x;
    if (id < XS_Q) {
        int i8 = id * 8;
        int n = i8 >> 11;
        int b = (i8 >> 6) & 31;
        int u = i8 & 63;
        const float* sp = state + (size_t)b * S_STRIDE + n * 64 + u;
        float4 s0 = *(const float4*)sp;
        float4 s1 = *(const float4*)(sp + 4);
        uint4 o;
        ((__half2*)&o)[0] = __floats2half2_rn(s0.x, s0.y);
        ((__half2*)&o)[1] = __floats2half2_rn(s0.z, s0.w);
        ((__half2*)&o)[2] = __floats2half2_rn(s1.x, s1.y);
        ((__half2*)&o)[3] = __floats2half2_rn(s1.z, s1.w);
        ((uint4*)g_XSh)[id] = o;
    } else {
        int j = id - XS_Q;
        if (j < N_NODES * NB) {
            int b = j / N_NODES, n = j - b * N_NODES;
            float2 v = *(const float2*)&inputs[b * 20000 + 2 * n];
            g_XI[n * 32 + b] = v;
        }
    }
}

// ---------------- SpMM (inputs part, once) ----------------
__global__ void k_spmm_in() {
    int gw = (blockIdx.x * 256 + threadIdx.x) >> 5;
    int lane = threadIdx.x & 31;
    if (gw >= N_NODES) return;
    int beg = __ldg(&g_rowptr[gw]), end = __ldg(&g_rowptr[gw + 1]);
    float2 acc = make_float2(0.f, 0.f);
    for (int e = beg; e < end; e++) {
        int c = __ldg(&g_col[e]);
        float v = __ldg(&g_val[e]);
        float2 x = g_XI[c * 32 + lane];
        acc.x = fmaf(v, x.x, acc.x);
        acc.y = fmaf(v, x.y, acc.y);
    }
    g_YI[gw * 32 + lane] = acc;
}

// ---------------- SpMM (state part): 2 blocks/row, 128 threads ----------------
// PASS selects buffers INSIDE device code — __device__ globals must never be
// passed as kernel arguments from host (host shadow address + GB300 ATS
// silently reads host zeros; that was the round-5/6 corruption).
__device__ __forceinline__ void acc8(float* a, uint4 q, float v) {
    float2 f0 = __half22float2(*(__half2*)&q.x);
    float2 f1 = __half22float2(*(__half2*)&q.y);
    float2 f2 = __half22float2(*(__half2*)&q.z);
    float2 f3 = __half22float2(*(__half2*)&q.w);
    a[0] = fmaf(v, f0.x, a[0]); a[1] = fmaf(v, f0.y, a[1]);
    a[2] = fmaf(v, f1.x, a[2]); a[3] = fmaf(v, f1.y, a[3]);
    a[4] = fmaf(v, f2.x, a[4]); a[5] = fmaf(v, f2.y, a[5]);
    a[6] = fmaf(v, f3.x, a[6]); a[7] = fmaf(v, f3.y, a[7]);
}

template <int PASS>
__global__ void __launch_bounds__(128, 10) k_spmm_s(int node_base) {
    const uint4* __restrict__ X = (const uint4*)(PASS == 0 ? g_XSh : g_XS2h);
    uint4* __restrict__ Y = (uint4*)(PASS == 0 ? g_X1h : g_X2h);
    int n = node_base + (blockIdx.x >> 1);
    int slot = ((blockIdx.x & 1) << 7) + threadIdx.x;   // uint4 index within row
    int t = threadIdx.x;
    __shared__ int   scol[128];
    __shared__ float sval[128];
    float a[8] = {0.f, 0.f, 0.f, 0.f, 0.f, 0.f, 0.f, 0.f};
    int beg = __ldg(&g_rowptr[n]), end = __ldg(&g_rowptr[n + 1]);
    for (int base = beg; base < end; base += 128) {
        int cnt = min(128, end - base);
        __syncthreads();
        if (t < cnt) { scol[t] = g_col[base + t]; sval[t] = g_val[base + t]; }
        __syncthreads();
        int e = 0;
        for (; e + 4 <= cnt; e += 4) {
            uint4 q0 = X[(size_t)scol[e + 0] * SROWQ + slot];
            uint4 q1 = X[(size_t)scol[e + 1] * SROWQ + slot];
            uint4 q2 = X[(size_t)scol[e + 2] * SROWQ + slot];
            uint4 q3 = X[(size_t)scol[e + 3] * SROWQ + slot];
            acc8(a, q0, sval[e + 0]);
            acc8(a, q1, sval[e + 1]);
            acc8(a, q2, sval[e + 2]);
            acc8(a, q3, sval[e + 3]);
        }
        for (; e < cnt; e++) {
            uint4 q = X[(size_t)scol[e] * SROWQ + slot];
            acc8(a, q, sval[e]);
        }
    }
    uint4 o;
    ((__half2*)&o)[0] = __floats2half2_rn(a[0], a[1]);
    ((__half2*)&o)[1] = __floats2half2_rn(a[2], a[3]);
    ((__half2*)&o)[2] = __floats2half2_rn(a[4], a[5]);
    ((__half2*)&o)[3] = __floats2half2_rn(a[6], a[7]);
    Y[(size_t)n * SROWQ + slot] = o;
}

// ---------------- shared xs fill (conflict-free, padded stride 66) ----------------
__device__ __forceinline__ void fill_xs(float xs[NF][66], int tid, int B0,
                                        const __half* __restrict__ X1src) {
    const uint2* src = (const uint2*)(X1src + (size_t)B0 * 4096);
#pragma unroll
    for (int k = 0; k < 8; k++) {
        int idx4 = tid + k * 128;        // 1024 uint2 = 64 rows x 16
        int r = idx4 >> 4;
        int u = (idx4 & 15) * 4;
        uint2 q = src[idx4];
        float2 f0 = __half22float2(*(__half2*)&q.x);
        float2 f1 = __half22float2(*(__half2*)&q.y);
        xs[u + 2][r] = f0.x; xs[u + 3][r] = f0.y;
        xs[u + 4][r] = f1.x; xs[u + 5][r] = f1.y;
    }
    {
        int r = tid >> 1, f = tid & 1;
        int node = 2 * B0 + (r >> 5), b = r & 31;
        float2 y = g_YI[node * 32 + b];
        xs[f][r] = f ? y.y : y.x;
    }
}

// ---------------- GEMM1 fused: sigmoid; r*state -> g_XS2h, u -> g_Uh ----------------
__global__ void __launch_bounds__(128) k_gemm1f(const float* __restrict__ w,
                                                const float* __restrict__ bias,
                                                int b0_base) {
    __shared__ float xs[NF][66];
    __shared__ float ws[NF * NU2];
    int tid = threadIdx.x;
    int B0 = b0_base + blockIdx.x;       // nodes 2B0, 2B0+1
    for (int i = tid; i < NF * NU2; i += 128) ws[i] = w[i];
    fill_xs(xs, tid, B0, g_X1h);
    __syncthreads();
    int tx = tid & 15, ty = tid >> 4;
    ull acc[4][8];
#pragma unroll
    for (int i = 0; i < 4; i++)
#pragma unroll
        for (int j = 0; j < 8; j++) acc[i][j] = 0ull;

#pragma unroll 2
    for (int f = 0; f < NF; f++) {
        ull a[4];
#pragma unroll
        for (int rp = 0; rp < 4; rp++)
            a[rp] = *(const ull*)&xs[f][ty * 8 + rp * 2];
        float4 w0 = *(const float4*)&ws[f * NU2 + tx * 8];
        float4 w1 = *(const float4*)&ws[f * NU2 + tx * 8 + 4];
        ull wd[8];
        wd[0] = pk2(w0.x, w0.x); wd[1] = pk2(w0.y, w0.y);
        wd[2] = pk2(w0.z, w0.z); wd[3] = pk2(w0.w, w0.w);
        wd[4] = pk2(w1.x, w1.x); wd[5] = pk2(w1.y, w1.y);
        wd[6] = pk2(w1.z, w1.z); wd[7] = pk2(w1.w, w1.w);
#pragma unroll
        for (int rp = 0; rp < 4; rp++)
#pragma unroll
            for (int j = 0; j < 8; j++) fma2(acc[rp][j], a[rp], wd[j]);
    }

    float bz[8];
    {
        float4 bb0 = *(const float4*)&bias[tx * 8];
        float4 bb1 = *(const float4*)&bias[tx * 8 + 4];
        bz[0] = bb0.x; bz[1] = bb0.y; bz[2] = bb0.z; bz[3] = bb0.w;
        bz[4] = bb1.x; bz[5] = bb1.y; bz[6] = bb1.z; bz[7] = bb1.w;
    }
    bool rside = (B0 < 2500);
#pragma unroll
    for (int rp = 0; rp < 4; rp++) {
#pragma unroll
        for (int h = 0; h < 2; h++) {
            int r = ty * 8 + rp * 2 + h;
            int nn = 2 * B0 + (r >> 5);
            int b = r & 31;
            float v[8];
#pragma unroll
            for (int j = 0; j < 8; j++) {
                float lo, hi; upk2(acc[rp][j], lo, hi);
                v[j] = sigf((h ? hi : lo) + bz[j]);
            }
            if (rside) {
                int t = 2 * nn + (tx >> 3);
                int c = (tx & 7) * 8;
                size_t off = (size_t)t * SROW + b * 64 + c;
                uint4 sh = *(const uint4*)&g_XSh[off];     // fp16 state (read-only buffer)
                float2 s0 = __half22float2(((__half2*)&sh)[0]);
                float2 s1 = __half22float2(((__half2*)&sh)[1]);
                float2 s2 = __half22float2(((__half2*)&sh)[2]);
                float2 s3 = __half22float2(((__half2*)&sh)[3]);
                uint4 o;
                ((__half2*)&o)[0] = __floats2half2_rn(v[0] * s0.x, v[1] * s0.y);
                ((__half2*)&o)[1] = __floats2half2_rn(v[2] * s1.x, v[3] * s1.y);
                ((__half2*)&o)[2] = __floats2half2_rn(v[4] * s2.x, v[5] * s2.y);
                ((__half2*)&o)[3] = __floats2half2_rn(v[6] * s3.x, v[7] * s3.y);
                *(uint4*)&g_XS2h[off] = o;                 // double buffer for pass 2
            } else {
                uint4 o;
                ((__half2*)&o)[0] = __floats2half2_rn(v[0], v[1]);
                ((__half2*)&o)[1] = __floats2half2_rn(v[2], v[3]);
                ((__half2*)&o)[2] = __floats2half2_rn(v[4], v[5]);
                ((__half2*)&o)[3] = __floats2half2_rn(v[6], v[7]);
                __stcs((uint4*)&g_Uh[(size_t)b * S_STRIDE + (nn - 5000) * 128 + tx * 8], o);
            }
        }
    }
}

// ---------------- GEMM2 + GRU combine ----------------
__global__ void __launch_bounds__(128) k_gemm2(const float* __restrict__ w,
                                               const float* __restrict__ bias,
                                               const float* __restrict__ state,
                                               float* __restrict__ out,
                                               int b0_base) {
    __shared__ float xs[NF][66];
    __shared__ float ws[NF * NU];
    int tid = threadIdx.x;
    int B0 = b0_base + blockIdx.x;
    for (int i = tid; i < NF * NU; i += 128) ws[i] = w[i];
    fill_xs(xs, tid, B0, g_X2h);
    __syncthreads();
    int tx = tid & 15, ty = tid >> 4;
    ull acc[4][4];
#pragma unroll
    for (int i = 0; i < 4; i++)
#pragma unroll
        for (int j = 0; j < 4; j++) acc[i][j] = 0ull;

#pragma unroll 2
    for (int f = 0; f < NF; f++) {
        ull a[4];
#pragma unroll
        for (int rp = 0; rp < 4; rp++)
            a[rp] = *(const ull*)&xs[f][ty * 8 + rp * 2];
        float4 w4 = *(const float4*)&ws[f * NU + tx * 4];
        ull wd[4];
        wd[0] = pk2(w4.x, w4.x); wd[1] = pk2(w4.y, w4.y);
        wd[2] = pk2(w4.z, w4.z); wd[3] = pk2(w4.w, w4.w);
#pragma unroll
        for (int rp = 0; rp < 4; rp++)
#pragma unroll
            for (int j = 0; j < 4; j++) fma2(acc[rp][j], a[rp], wd[j]);
    }

    float4 bb = *(const float4*)&bias[tx * 4];
    float bz[4] = {bb.x, bb.y, bb.z, bb.w};
#pragma unroll
    for (int rp = 0; rp < 4; rp++) {
#pragma unroll
        for (int h = 0; h < 2; h++) {
            int r = ty * 8 + rp * 2 + h;
            int n = 2 * B0 + (r >> 5), b = r & 31;
            size_t j = (size_t)b * S_STRIDE + n * 64 + tx * 4;
            float c[4];
#pragma unroll
            for (int q = 0; q < 4; q++) {
                float lo, hi; upk2(acc[rp][q], lo, hi);
                c[q] = fmaxf((h ? hi : lo) + bz[q], 0.0f);
            }
            uint2 uh = __ldcs((const uint2*)&g_Uh[j]);
            float2 u0 = __half22float2(*(__half2*)&uh.x);
            float2 u1 = __half22float2(*(__half2*)&uh.y);
            float4 s4 = *(const float4*)&state[j];
            float4 o;
            o.x = u0.x * s4.x + (1.0f - u0.x) * c[0];
            o.y = u0.y * s4.y + (1.0f - u0.y) * c[1];
            o.z = u1.x * s4.z + (1.0f - u1.x) * c[2];
            o.w = u1.y * s4.w + (1.0f - u1.y) * c[3];
            *(float4*)&out[j] = o;
        }
    }
}

// ---------------- launch: half-grain pipeline across two streams ----------------
extern "C" void kernel_launch(void* const* d_in, const int* in_sizes, int n_in,
                              void* d_out, int out_size) {
    const float* inputs = (const float*)d_in[0];
    const float* state  = (const float*)d_in[1];
    const int*   m_rows = (const int*)d_in[2];
    const int*   m_cols = (const int*)d_in[3];
    const float* m_vals = (const float*)d_in[4];
    const float* w1     = (const float*)d_in[5];
    const float* b1     = (const float*)d_in[6];
    const float* w2     = (const float*)d_in[7];
    const float* b2     = (const float*)d_in[8];
    float* out = (float*)d_out;
    int nnz = in_sizes[2];

    // fork: builder on side stream, CSR chain on main
    cudaEventRecord(g_evFork, 0);
    cudaStreamWaitEvent(g_s1, g_evFork, 0);
    k_build<<<(XS_Q + N_NODES * NB + 255) / 256, 256, 0, g_s1>>>(inputs, state);
    cudaEventRecord(g_evBuild, g_s1);

    k_zero<<<(N_NODES + 255) / 256, 256>>>();
    k_hist<<<(nnz + 255) / 256, 256>>>(m_rows, nnz);
    k_scan<<<1, 1024>>>();
    k_scatter<<<(nnz + 255) / 256, 256>>>(m_rows, m_cols, m_vals, nnz);
    cudaEventRecord(g_evCsr, 0);

    // side: inputs-part SpMM (needs CSR; build already ordered on g_s1)
    cudaStreamWaitEvent(g_s1, g_evCsr, 0);
    k_spmm_in<<<(N_NODES * 32 + 255) / 256, 256, 0, g_s1>>>();

    // main: SpMM1 halves (need build + CSR); 10000 blocks each (~6.8 waves)
    cudaStreamWaitEvent(0, g_evBuild, 0);
    for (int h = 0; h < 2; h++) {
        k_spmm_s<0><<<2 * HALF_NODES, 128>>>(h * HALF_NODES);
        cudaEventRecord(g_evS1[h], 0);
    }

    // side: GEMM1-r (nodes 0..4999 -> needs S1 half 0), then GEMM1-u (needs S1 half 1)
    cudaStreamWaitEvent(g_s1, g_evS1[0], 0);
    k_gemm1f<<<2500, 128, 0, g_s1>>>(w1, b1, 0);        // writes ALL of g_XS2h
    cudaEventRecord(g_evG1r, g_s1);
    cudaStreamWaitEvent(g_s1, g_evS1[1], 0);
    k_gemm1f<<<2500, 128, 0, g_s1>>>(w1, b1, 2500);     // writes g_Uh (overlaps SpMM2)

    // main: SpMM2 halves (need g_XS2h complete = GEMM1-r); write g_X2h (disjoint from g_X1h)
    cudaStreamWaitEvent(0, g_evG1r, 0);
    for (int h = 0; h < 2; h++) {
        k_spmm_s<1><<<2 * HALF_NODES, 128>>>(h * HALF_NODES);
        cudaEventRecord(g_evS2[h], 0);
    }

    // side: GEMM2 halves behind their SpMM2 halves (g_Uh ordered in-stream after GEMM1-u)
    for (int h = 0; h < 2; h++) {
        cudaStreamWaitEvent(g_s1, g_evS2[h], 0);
        k_gemm2<<<2500, 128, 0, g_s1>>>(w2, b2, state, out, h * 2500);
    }
    cudaEventRecord(g_evDone, g_s1);
    cudaStreamWaitEvent(0, g_evDone, 0);   // join back to capture origin stream
}

// round 9
// speedup vs baseline: 1.3758x; 1.2099x over previous
#include <cuda_runtime.h>
#include <cuda_fp16.h>

#define N_NODES 10000
#define NB 32
#define SROW 2048            // halves per node row (state part)
#define SROWQ 256            // uint4 per row
#define NNZ_MAX 330000
#define XS_ELEMS (N_NODES * SROW)
#define S_STRIDE 640000      // N*NU per batch
#define XS_Q (XS_ELEMS / 8)

__device__ __half  g_XSh[XS_ELEMS];        // pass-1 gather source; rewritten in-place to r*state by GEMM1
__device__ __half  g_X1h[XS_ELEMS];        // spmm output (both passes)
__device__ float2  g_XI[N_NODES * NB];     // inputs-part gather source
__device__ float2  g_YI[N_NODES * NB];     // inputs-part spmm result (reused by both gc's)
__device__ __half  g_Uh[NB * S_STRIDE];    // update gate
__device__ __half  g_wT1[128 * 88];        // w1 transposed fp16, n-major, K zero-padded to 80 (stride 88)
__device__ __half  g_wT2[64 * 88];         // w2 likewise
__device__ int     g_cnt[N_NODES];
__device__ int     g_cur[N_NODES];
__device__ int     g_rowptr[N_NODES + 1];
__device__ int     g_col[NNZ_MAX];
__device__ float   g_val[NNZ_MAX];

// ---------- streams/events (static init; no device memory) ----------
static cudaStream_t g_s1;
static cudaEvent_t  g_evFork, g_evBuild, g_evCsr, g_evIn;
namespace {
struct HxInit {
    HxInit() {
        cudaStreamCreateWithFlags(&g_s1, cudaStreamNonBlocking);
        cudaEventCreateWithFlags(&g_evFork,  cudaEventDisableTiming);
        cudaEventCreateWithFlags(&g_evBuild, cudaEventDisableTiming);
        cudaEventCreateWithFlags(&g_evCsr,   cudaEventDisableTiming);
        cudaEventCreateWithFlags(&g_evIn,    cudaEventDisableTiming);
    }
};
static HxInit g_hxinit;
}

__device__ __forceinline__ float sigf(float x) { return 1.0f / (1.0f + __expf(-x)); }

// ---------------- CSR build ----------------
__global__ void k_zero() {
    int i = blockIdx.x * blockDim.x + threadIdx.x;
    if (i < N_NODES) { g_cnt[i] = 0; g_cur[i] = 0; }
}
__global__ void k_hist(const int* __restrict__ rows, int nnz) {
    int i = blockIdx.x * blockDim.x + threadIdx.x;
    if (i < nnz) atomicAdd(&g_cnt[rows[i]], 1);
}
__global__ void k_scan() {
    __shared__ int s[1024];
    int tid = threadIdx.x;
    int loc[10];
    int sum = 0;
#pragma unroll
    for (int k = 0; k < 10; k++) {
        int i = tid * 10 + k;
        int v = (i < N_NODES) ? g_cnt[i] : 0;
        loc[k] = v; sum += v;
    }
    s[tid] = sum;
    __syncthreads();
    for (int d = 1; d < 1024; d <<= 1) {
        int v = (tid >= d) ? s[tid - d] : 0;
        __syncthreads();
        s[tid] += v;
        __syncthreads();
    }
    int run = s[tid] - sum;
#pragma unroll
    for (int k = 0; k < 10; k++) {
        int i = tid * 10 + k;
        if (i < N_NODES) g_rowptr[i] = run;
        run += loc[k];
    }
    if (tid == 1023) g_rowptr[N_NODES] = run;
}
__global__ void k_scatter(const int* __restrict__ rows, const int* __restrict__ cols,
                          const float* __restrict__ vals, int nnz) {
    int i = blockIdx.x * blockDim.x + threadIdx.x;
    if (i < nnz) {
        int r = rows[i];
        int p = g_rowptr[r] + atomicAdd(&g_cur[r], 1);
        g_col[p] = cols[i];
        g_val[p] = vals[i];
    }
}

// ---------------- weight transpose/pad (once, tiny) ----------------
__global__ void k_wprep(const float* __restrict__ w1, const float* __restrict__ w2) {
    int tid = blockIdx.x * 256 + threadIdx.x;
    if (tid < 128 * 88) {
        int n = tid / 88, k = tid - n * 88;
        g_wT1[tid] = __float2half((k < 66) ? w1[k * 128 + n] : 0.0f);
    } else if (tid < 128 * 88 + 64 * 88) {
        int j = tid - 128 * 88;
        int n = j / 88, k = j - n * 88;
        g_wT2[j] = __float2half((k < 66) ? w2[k * 64 + n] : 0.0f);
    }
}

// ---------------- fused builder (XS fp16 + XI) ----------------
__global__ void k_build(const float* __restrict__ inputs, const float* __restrict__ state) {
    int id = blockIdx.x * 256 + threadIdx.x;
    if (id < XS_Q) {
        int i8 = id * 8;
        int n = i8 >> 11;
        int b = (i8 >> 6) & 31;
        int u = i8 & 63;
        const float* sp = state + (size_t)b * S_STRIDE + n * 64 + u;
        float4 s0 = *(const float4*)sp;
        float4 s1 = *(const float4*)(sp + 4);
        uint4 o;
        ((__half2*)&o)[0] = __floats2half2_rn(s0.x, s0.y);
        ((__half2*)&o)[1] = __floats2half2_rn(s0.z, s0.w);
        ((__half2*)&o)[2] = __floats2half2_rn(s1.x, s1.y);
        ((__half2*)&o)[3] = __floats2half2_rn(s1.z, s1.w);
        ((uint4*)g_XSh)[id] = o;
    } else {
        int j = id - XS_Q;
        if (j < N_NODES * NB) {
            int b = j / N_NODES, n = j - b * N_NODES;
            float2 v = *(const float2*)&inputs[b * 20000 + 2 * n];
            g_XI[n * 32 + b] = v;
        }
    }
}

// ---------------- SpMM (inputs part, once) ----------------
__global__ void k_spmm_in() {
    int gw = (blockIdx.x * 256 + threadIdx.x) >> 5;
    int lane = threadIdx.x & 31;
    if (gw >= N_NODES) return;
    int beg = __ldg(&g_rowptr[gw]), end = __ldg(&g_rowptr[gw + 1]);
    float2 acc = make_float2(0.f, 0.f);
    for (int e = beg; e < end; e++) {
        int c = __ldg(&g_col[e]);
        float v = __ldg(&g_val[e]);
        float2 x = g_XI[c * 32 + lane];
        acc.x = fmaf(v, x.x, acc.x);
        acc.y = fmaf(v, x.y, acc.y);
    }
    g_YI[gw * 32 + lane] = acc;
}

// ---------------- SpMM (state part): 2 blocks/row, 128 threads ----------------
// Buffers referenced ONLY in device code (never as host-side kernel args).
__device__ __forceinline__ void acc8(float* a, uint4 q, float v) {
    float2 f0 = __half22float2(*(__half2*)&q.x);
    float2 f1 = __half22float2(*(__half2*)&q.y);
    float2 f2 = __half22float2(*(__half2*)&q.z);
    float2 f3 = __half22float2(*(__half2*)&q.w);
    a[0] = fmaf(v, f0.x, a[0]); a[1] = fmaf(v, f0.y, a[1]);
    a[2] = fmaf(v, f1.x, a[2]); a[3] = fmaf(v, f1.y, a[3]);
    a[4] = fmaf(v, f2.x, a[4]); a[5] = fmaf(v, f2.y, a[5]);
    a[6] = fmaf(v, f3.x, a[6]); a[7] = fmaf(v, f3.y, a[7]);
}

__global__ void __launch_bounds__(128, 10) k_spmm_s() {
    const uint4* __restrict__ X = (const uint4*)g_XSh;
    int n = blockIdx.x >> 1;
    int slot = ((blockIdx.x & 1) << 7) + threadIdx.x;
    int t = threadIdx.x;
    __shared__ int   scol[128];
    __shared__ float sval[128];
    float a[8] = {0.f, 0.f, 0.f, 0.f, 0.f, 0.f, 0.f, 0.f};
    int beg = __ldg(&g_rowptr[n]), end = __ldg(&g_rowptr[n + 1]);
    for (int base = beg; base < end; base += 128) {
        int cnt = min(128, end - base);
        __syncthreads();
        if (t < cnt) { scol[t] = g_col[base + t]; sval[t] = g_val[base + t]; }
        __syncthreads();
        int e = 0;
        for (; e + 4 <= cnt; e += 4) {
            uint4 q0 = X[(size_t)scol[e + 0] * SROWQ + slot];
            uint4 q1 = X[(size_t)scol[e + 1] * SROWQ + slot];
            uint4 q2 = X[(size_t)scol[e + 2] * SROWQ + slot];
            uint4 q3 = X[(size_t)scol[e + 3] * SROWQ + slot];
            acc8(a, q0, sval[e + 0]);
            acc8(a, q1, sval[e + 1]);
            acc8(a, q2, sval[e + 2]);
            acc8(a, q3, sval[e + 3]);
        }
        for (; e < cnt; e++) {
            uint4 q = X[(size_t)scol[e] * SROWQ + slot];
            acc8(a, q, sval[e]);
        }
    }
    uint4 o;
    ((__half2*)&o)[0] = __floats2half2_rn(a[0], a[1]);
    ((__half2*)&o)[1] = __floats2half2_rn(a[2], a[3]);
    ((__half2*)&o)[2] = __floats2half2_rn(a[4], a[5]);
    ((__half2*)&o)[3] = __floats2half2_rn(a[6], a[7]);
    ((uint4*)g_X1h)[(size_t)n * SROWQ + slot] = o;
}

// ---------------- HMMA helpers ----------------
__device__ __forceinline__ void mma16816(float* c, const unsigned* a, const unsigned* b) {
    asm volatile(
        "mma.sync.aligned.m16n8k16.row.col.f32.f16.f16.f32 "
        "{%0,%1,%2,%3}, {%4,%5,%6,%7}, {%8,%9}, {%0,%1,%2,%3};"
        : "+f"(c[0]), "+f"(c[1]), "+f"(c[2]), "+f"(c[3])
        : "r"(a[0]), "r"(a[1]), "r"(a[2]), "r"(a[3]), "r"(b[0]), "r"(b[1]));
}

// A tile [64 rows][88 halves] (cols 0..1 = inputs-part, 2..65 = spmm, 66..79 = zero)
__device__ __forceinline__ void fill_xs16(__half* xs, int tid, int B0) {
    const uint4* src = (const uint4*)(g_X1h + (size_t)B0 * 4096);
#pragma unroll
    for (int k = 0; k < 4; k++) {
        int idx = tid + k * 128;          // 512 uint4 = 64 rows x 8
        int r = idx >> 3, seg = idx & 7;
        uint4 q = __ldcs(&src[idx]);
        unsigned* p = (unsigned*)&xs[r * 88 + 2 + seg * 8];
        p[0] = q.x; p[1] = q.y; p[2] = q.z; p[3] = q.w;
    }
    if (tid < 64) {
        int r = tid;
        int node = 2 * B0 + (r >> 5), b = r & 31;
        float2 y = g_YI[node * 32 + b];
        xs[r * 88]     = __float2half(y.x);
        xs[r * 88 + 1] = __float2half(y.y);
    } else {
        int r = tid - 64;
        unsigned* p = (unsigned*)&xs[r * 88 + 66];
#pragma unroll
        for (int i = 0; i < 7; i++) p[i] = 0u;   // zero cols 66..79
    }
}

// ---------------- GEMM1 (HMMA): sigmoid; r*state in-place -> g_XSh, u -> g_Uh ----------------
__global__ void __launch_bounds__(128, 4) k_gemm1f(const float* __restrict__ bias) {
    __shared__ __half xs[64 * 88];
    int tid = threadIdx.x;
    int B0 = blockIdx.x;                 // nodes 2B0, 2B0+1
    fill_xs16(xs, tid, B0);
    __syncthreads();
    int lane = tid & 31, w = tid >> 5;
    int g = lane >> 2, tig = lane & 3;
    float acc[4][4][4] = {};
#pragma unroll
    for (int ks = 0; ks < 5; ks++) {
        int k0 = ks * 16 + 2 * tig;
        unsigned af[4][4];
#pragma unroll
        for (int mt = 0; mt < 4; mt++) {
            int m = g + 16 * mt;
            af[mt][0] = *(const unsigned*)&xs[m * 88 + k0];
            af[mt][1] = *(const unsigned*)&xs[(m + 8) * 88 + k0];
            af[mt][2] = *(const unsigned*)&xs[m * 88 + k0 + 8];
            af[mt][3] = *(const unsigned*)&xs[(m + 8) * 88 + k0 + 8];
        }
        unsigned bf[4][2];
#pragma unroll
        for (int nt = 0; nt < 4; nt++) {
            int n = 32 * w + 8 * nt + g;
            bf[nt][0] = __ldg((const unsigned*)&g_wT1[n * 88 + k0]);
            bf[nt][1] = __ldg((const unsigned*)&g_wT1[n * 88 + k0 + 8]);
        }
#pragma unroll
        for (int mt = 0; mt < 4; mt++)
#pragma unroll
            for (int nt = 0; nt < 4; nt++)
                mma16816(acc[mt][nt], af[mt], bf[nt]);
    }
    bool rside = (B0 < 2500);
#pragma unroll
    for (int nt = 0; nt < 4; nt++) {
        int j = 32 * w + 8 * nt + 2 * tig;         // cols j, j+1
        float2 bb = *(const float2*)&bias[j];
#pragma unroll
        for (int mt = 0; mt < 4; mt++) {
#pragma unroll
            for (int h = 0; h < 2; h++) {
                int m = g + 16 * mt + 8 * h;
                int nn = 2 * B0 + (m >> 5), b = m & 31;
                float v0 = sigf(acc[mt][nt][2 * h]     + bb.x);
                float v1 = sigf(acc[mt][nt][2 * h + 1] + bb.y);
                if (rside) {
                    int tt = 2 * nn + (j >> 6);
                    size_t off = (size_t)tt * SROW + b * 64 + (j & 63);
                    float2 s = __half22float2(*(__half2*)&g_XSh[off]);
                    *(__half2*)&g_XSh[off] = __floats2half2_rn(v0 * s.x, v1 * s.y);
                } else {
                    size_t off = (size_t)b * S_STRIDE + (nn - 5000) * 128 + j;
                    __half2 hv = __floats2half2_rn(v0, v1);
                    __stcs((unsigned*)&g_Uh[off], *(unsigned*)&hv);
                }
            }
        }
    }
}

// ---------------- GEMM2 (HMMA) + GRU combine ----------------
__global__ void __launch_bounds__(128, 5) k_gemm2(const float* __restrict__ bias,
                                                  const float* __restrict__ state,
                                                  float* __restrict__ out) {
    __shared__ __half xs[64 * 88];
    int tid = threadIdx.x;
    int B0 = blockIdx.x;
    fill_xs16(xs, tid, B0);
    __syncthreads();
    int lane = tid & 31, w = tid >> 5;
    int g = lane >> 2, tig = lane & 3;
    float acc[4][2][4] = {};
#pragma unroll
    for (int ks = 0; ks < 5; ks++) {
        int k0 = ks * 16 + 2 * tig;
        unsigned af[4][4];
#pragma unroll
        for (int mt = 0; mt < 4; mt++) {
            int m = g + 16 * mt;
            af[mt][0] = *(const unsigned*)&xs[m * 88 + k0];
            af[mt][1] = *(const unsigned*)&xs[(m + 8) * 88 + k0];
            af[mt][2] = *(const unsigned*)&xs[m * 88 + k0 + 8];
            af[mt][3] = *(const unsigned*)&xs[(m + 8) * 88 + k0 + 8];
        }
        unsigned bf[2][2];
#pragma unroll
        for (int nt = 0; nt < 2; nt++) {
            int n = 16 * w + 8 * nt + g;
            bf[nt][0] = __ldg((const unsigned*)&g_wT2[n * 88 + k0]);
            bf[nt][1] = __ldg((const unsigned*)&g_wT2[n * 88 + k0 + 8]);
        }
#pragma unroll
        for (int mt = 0; mt < 4; mt++)
#pragma unroll
            for (int nt = 0; nt < 2; nt++)
                mma16816(acc[mt][nt], af[mt], bf[nt]);
    }
#pragma unroll
    for (int nt = 0; nt < 2; nt++) {
        int j = 16 * w + 8 * nt + 2 * tig;         // cols j, j+1 (0..63)
        float2 bb = *(const float2*)&bias[j];
#pragma unroll
        for (int mt = 0; mt < 4; mt++) {
#pragma unroll
            for (int h = 0; h < 2; h++) {
                int m = g + 16 * mt + 8 * h;
                int nn = 2 * B0 + (m >> 5), b = m & 31;
                float c0 = fmaxf(acc[mt][nt][2 * h]     + bb.x, 0.0f);
                float c1 = fmaxf(acc[mt][nt][2 * h + 1] + bb.y, 0.0f);
                size_t off = (size_t)b * S_STRIDE + nn * 64 + j;
                unsigned uu = __ldcs((const unsigned*)&g_Uh[off]);
                float2 u = __half22float2(*(__half2*)&uu);
                float2 s = *(const float2*)&state[off];
                float2 o;
                o.x = u.x * s.x + (1.0f - u.x) * c0;
                o.y = u.y * s.y + (1.0f - u.y) * c1;
                *(float2*)&out[off] = o;
            }
        }
    }
}

// ---------------- launch: serial main chain + harmless side-fork ----------------
extern "C" void kernel_launch(void* const* d_in, const int* in_sizes, int n_in,
                              void* d_out, int out_size) {
    const float* inputs = (const float*)d_in[0];
    const float* state  = (const float*)d_in[1];
    const int*   m_rows = (const int*)d_in[2];
    const int*   m_cols = (const int*)d_in[3];
    const float* m_vals = (const float*)d_in[4];
    const float* w1     = (const float*)d_in[5];
    const float* b1     = (const float*)d_in[6];
    const float* w2     = (const float*)d_in[7];
    const float* b2     = (const float*)d_in[8];
    float* out = (float*)d_out;
    int nnz = in_sizes[2];

    // side: weight prep + builder, parallel with CSR chain
    cudaEventRecord(g_evFork, 0);
    cudaStreamWaitEvent(g_s1, g_evFork, 0);
    k_wprep<<<66, 256, 0, g_s1>>>(w1, w2);
    k_build<<<(XS_Q + N_NODES * NB + 255) / 256, 256, 0, g_s1>>>(inputs, state);
    cudaEventRecord(g_evBuild, g_s1);

    k_zero<<<(N_NODES + 255) / 256, 256>>>();
    k_hist<<<(nnz + 255) / 256, 256>>>(m_rows, nnz);
    k_scan<<<1, 1024>>>();
    k_scatter<<<(nnz + 255) / 256, 256>>>(m_rows, m_cols, m_vals, nnz);
    cudaEventRecord(g_evCsr, 0);

    // side: inputs-part SpMM (needs CSR; after build on same stream)
    cudaStreamWaitEvent(g_s1, g_evCsr, 0);
    k_spmm_in<<<(N_NODES * NB + 255) / 256, 256, 0, g_s1>>>();
    cudaEventRecord(g_evIn, g_s1);

    // main: strictly serial big phases (no SpMM/GEMM co-residency)
    cudaStreamWaitEvent(0, g_evBuild, 0);
    k_spmm_s<<<2 * N_NODES, 128>>>();          // pass 1: XSh -> X1h
    cudaStreamWaitEvent(0, g_evIn, 0);
    k_gemm1f<<<N_NODES / 2, 128>>>(b1);        // r*state in-place -> XSh, u -> Uh
    k_spmm_s<<<2 * N_NODES, 128>>>();          // pass 2: XSh -> X1h
    k_gemm2<<<N_NODES / 2, 128>>>(b2, state, out);
}

// round 10
// speedup vs baseline: 1.5353x; 1.1160x over previous
#include <cuda_runtime.h>
#include <cuda_fp16.h>

#define N_NODES 10000
#define NB 32
#define SROW 2048            // halves per node row (state part)
#define SROWQ 256            // uint4 per row
#define NNZ_MAX 330000
#define XS_ELEMS (N_NODES * SROW)
#define S_STRIDE 640000      // N*NU per batch
#define XS_Q (XS_ELEMS / 8)

__device__ __half  g_XSh[XS_ELEMS];        // pass-1 gather source (state fp16), read-only
__device__ __half  g_XS2h[XS_ELEMS];       // pass-2 gather source (r*state fp16)
__device__ float2  g_XI[N_NODES * NB];     // inputs-part gather source
__device__ float2  g_YI[N_NODES * NB];     // inputs-part spmm result (reused by both gc's)
__device__ __half  g_Uh[NB * S_STRIDE];    // update gate
__device__ __half  g_wT1[128 * 88];        // w1^T fp16, n-major, K padded 66->80 (stride 88)
__device__ __half  g_wT2[64 * 88];         // w2^T likewise
__device__ int     g_cnt[N_NODES];
__device__ int     g_cur[N_NODES];
__device__ int     g_rowptr[N_NODES + 1];
__device__ int     g_col[NNZ_MAX];
__device__ float   g_val[NNZ_MAX];

// ---------- streams/events (static init; no device memory) ----------
static cudaStream_t g_s1;
static cudaEvent_t  g_evFork, g_evCsr, g_evIn;
namespace {
struct HxInit {
    HxInit() {
        cudaStreamCreateWithFlags(&g_s1, cudaStreamNonBlocking);
        cudaEventCreateWithFlags(&g_evFork, cudaEventDisableTiming);
        cudaEventCreateWithFlags(&g_evCsr,  cudaEventDisableTiming);
        cudaEventCreateWithFlags(&g_evIn,   cudaEventDisableTiming);
    }
};
static HxInit g_hxinit;
}

__device__ __forceinline__ float sigf(float x) { return 1.0f / (1.0f + __expf(-x)); }

__device__ __forceinline__ void mma16816(float* c, const unsigned* a, const unsigned* b) {
    asm volatile(
        "mma.sync.aligned.m16n8k16.row.col.f32.f16.f16.f32 "
        "{%0,%1,%2,%3}, {%4,%5,%6,%7}, {%8,%9}, {%0,%1,%2,%3};"
        : "+f"(c[0]), "+f"(c[1]), "+f"(c[2]), "+f"(c[3])
        : "r"(a[0]), "r"(a[1]), "r"(a[2]), "r"(a[3]), "r"(b[0]), "r"(b[1]));
}

// ---------------- CSR build ----------------
__global__ void k_zero() {
    int i = blockIdx.x * blockDim.x + threadIdx.x;
    if (i < N_NODES) { g_cnt[i] = 0; g_cur[i] = 0; }
}
__global__ void k_hist(const int* __restrict__ rows, int nnz) {
    int i = blockIdx.x * blockDim.x + threadIdx.x;
    if (i < nnz) atomicAdd(&g_cnt[rows[i]], 1);
}
__global__ void k_scan() {   // 1024 threads, 2 barriers (warp-shuffle scan)
    __shared__ int wsum[32];
    int tid = threadIdx.x;
    int lane = tid & 31, wid = tid >> 5;
    int loc[10];
    int sum = 0;
#pragma unroll
    for (int k = 0; k < 10; k++) {
        int i = tid * 10 + k;
        int v = (i < N_NODES) ? g_cnt[i] : 0;
        loc[k] = v; sum += v;
    }
    int x = sum;
#pragma unroll
    for (int d = 1; d < 32; d <<= 1) {
        int y = __shfl_up_sync(0xffffffffu, x, d);
        if (lane >= d) x += y;
    }
    if (lane == 31) wsum[wid] = x;
    __syncthreads();
    if (wid == 0) {
        int y = wsum[lane];
#pragma unroll
        for (int d = 1; d < 32; d <<= 1) {
            int z = __shfl_up_sync(0xffffffffu, y, d);
            if (lane >= d) y += z;
        }
        wsum[lane] = y;
    }
    __syncthreads();
    int run = x - sum + (wid ? wsum[wid - 1] : 0);
#pragma unroll
    for (int k = 0; k < 10; k++) {
        int i = tid * 10 + k;
        if (i < N_NODES) g_rowptr[i] = run;
        run += loc[k];
    }
    if (tid == 1023) g_rowptr[N_NODES] = run;
}
__global__ void k_scatter(const int* __restrict__ rows, const int* __restrict__ cols,
                          const float* __restrict__ vals, int nnz) {
    int i = blockIdx.x * blockDim.x + threadIdx.x;
    if (i < nnz) {
        int r = rows[i];
        int p = g_rowptr[r] + atomicAdd(&g_cur[r], 1);
        g_col[p] = cols[i];
        g_val[p] = vals[i];
    }
}

// ---------------- weight transpose/pad (once, tiny) ----------------
__global__ void k_wprep(const float* __restrict__ w1, const float* __restrict__ w2) {
    int tid = blockIdx.x * 256 + threadIdx.x;
    if (tid < 128 * 88) {
        int n = tid / 88, k = tid - n * 88;
        g_wT1[tid] = __float2half((k < 66) ? w1[k * 128 + n] : 0.0f);
    } else if (tid < 128 * 88 + 64 * 88) {
        int j = tid - 128 * 88;
        int n = j / 88, k = j - n * 88;
        g_wT2[j] = __float2half((k < 66) ? w2[k * 64 + n] : 0.0f);
    }
}

// ---------------- fused builder (XS fp16 + XI) ----------------
__global__ void k_build(const float* __restrict__ inputs, const float* __restrict__ state) {
    int id = blockIdx.x * 256 + threadIdx.x;
    if (id < XS_Q) {
        int i8 = id * 8;
        int n = i8 >> 11;
        int b = (i8 >> 6) & 31;
        int u = i8 & 63;
        const float* sp = state + (size_t)b * S_STRIDE + n * 64 + u;
        float4 s0 = *(const float4*)sp;
        float4 s1 = *(const float4*)(sp + 4);
        uint4 o;
        ((__half2*)&o)[0] = __floats2half2_rn(s0.x, s0.y);
        ((__half2*)&o)[1] = __floats2half2_rn(s0.z, s0.w);
        ((__half2*)&o)[2] = __floats2half2_rn(s1.x, s1.y);
        ((__half2*)&o)[3] = __floats2half2_rn(s1.z, s1.w);
        ((uint4*)g_XSh)[id] = o;
    } else {
        int j = id - XS_Q;
        if (j < N_NODES * NB) {
            int b = j / N_NODES, n = j - b * N_NODES;
            float2 v = *(const float2*)&inputs[b * 20000 + 2 * n];
            g_XI[n * 32 + b] = v;
        }
    }
}

// ---------------- SpMM (inputs part, once) ----------------
__global__ void k_spmm_in() {
    int gw = (blockIdx.x * 256 + threadIdx.x) >> 5;
    int lane = threadIdx.x & 31;
    if (gw >= N_NODES) return;
    int beg = __ldg(&g_rowptr[gw]), end = __ldg(&g_rowptr[gw + 1]);
    float2 acc = make_float2(0.f, 0.f);
    for (int e = beg; e < end; e++) {
        int c = __ldg(&g_col[e]);
        float v = __ldg(&g_val[e]);
        float2 x = g_XI[c * 32 + lane];
        acc.x = fmaf(v, x.x, acc.x);
        acc.y = fmaf(v, x.y, acc.y);
    }
    g_YI[gw * 32 + lane] = acc;
}

// ---------------- shared gather body ----------------
__device__ __forceinline__ void acc8(float* a, uint4 q, float v) {
    float2 f0 = __half22float2(*(__half2*)&q.x);
    float2 f1 = __half22float2(*(__half2*)&q.y);
    float2 f2 = __half22float2(*(__half2*)&q.z);
    float2 f3 = __half22float2(*(__half2*)&q.w);
    a[0] = fmaf(v, f0.x, a[0]); a[1] = fmaf(v, f0.y, a[1]);
    a[2] = fmaf(v, f1.x, a[2]); a[3] = fmaf(v, f1.y, a[3]);
    a[4] = fmaf(v, f2.x, a[4]); a[5] = fmaf(v, f2.y, a[5]);
    a[6] = fmaf(v, f3.x, a[6]); a[7] = fmaf(v, f3.y, a[7]);
}

__device__ __forceinline__ void gather_row(const uint4* __restrict__ X, int n, int slot,
                                           int t, int* scol, float* sval, float* a) {
    int beg = __ldg(&g_rowptr[n]), end = __ldg(&g_rowptr[n + 1]);
    for (int base = beg; base < end; base += 128) {
        int cnt = min(128, end - base);
        __syncthreads();
        if (t < cnt) { scol[t] = g_col[base + t]; sval[t] = g_val[base + t]; }
        __syncthreads();
        int e = 0;
        for (; e + 4 <= cnt; e += 4) {
            uint4 q0 = X[(size_t)scol[e + 0] * SROWQ + slot];
            uint4 q1 = X[(size_t)scol[e + 1] * SROWQ + slot];
            uint4 q2 = X[(size_t)scol[e + 2] * SROWQ + slot];
            uint4 q3 = X[(size_t)scol[e + 3] * SROWQ + slot];
            acc8(a, q0, sval[e + 0]);
            acc8(a, q1, sval[e + 1]);
            acc8(a, q2, sval[e + 2]);
            acc8(a, q3, sval[e + 3]);
        }
        for (; e < cnt; e++) {
            uint4 q = X[(size_t)scol[e] * SROWQ + slot];
            acc8(a, q, sval[e]);
        }
    }
}

// Stage this block's 16x(2+64) tile (+zero pad to K=80) into A[16][88].
__device__ __forceinline__ void stage_A(__half* A, int n, int slot, const float* a) {
    int brow = slot >> 3;            // global batch 0..31
    int row = brow & 15;
    int colb = 2 + (slot & 7) * 8;
#pragma unroll
    for (int i = 0; i < 4; i++) {
        __half2 hv = __floats2half2_rn(a[2 * i], a[2 * i + 1]);
        *(unsigned*)&A[row * 88 + colb + 2 * i] = *(unsigned*)&hv;
    }
    int r7 = slot & 7;
    if (r7 == 0) {
        float2 y = g_YI[n * 32 + brow];
        __half2 hv = __floats2half2_rn(y.x, y.y);
        *(unsigned*)&A[row * 88] = *(unsigned*)&hv;
    } else if (r7 == 1) {
        unsigned* p = (unsigned*)&A[row * 88 + 66];
        p[0] = 0; p[1] = 0; p[2] = 0; p[3] = 0;      // halves 66..73
    } else if (r7 == 2) {
        unsigned* p = (unsigned*)&A[row * 88 + 74];
        p[0] = 0; p[1] = 0; p[2] = 0; p[3] = 0;      // halves 74..81 (79 is last read)
    }
}

// ---------------- pass 1: SpMM + GEMM1 + sigmoid; r*state -> XS2h, u -> Uh ----------------
__global__ void __launch_bounds__(128, 8) k_spmm1f(const float* __restrict__ bias) {
    __shared__ int    scol[128];
    __shared__ float  sval[128];
    __shared__ __half A[16 * 88];
    int n = blockIdx.x >> 1;
    int h0 = blockIdx.x & 1;
    int tid = threadIdx.x;
    int slot = (h0 << 7) + tid;
    float a[8] = {0.f, 0.f, 0.f, 0.f, 0.f, 0.f, 0.f, 0.f};
    gather_row((const uint4*)g_XSh, n, slot, tid, scol, sval, a);
    stage_A(A, n, slot, a);
    __syncthreads();

    int lane = tid & 31, w = tid >> 5;
    int g = lane >> 2, tig = lane & 3;
    float acc[4][4] = {};
#pragma unroll
    for (int ks = 0; ks < 5; ks++) {
        int k0 = ks * 16 + 2 * tig;
        unsigned af[4];
        af[0] = *(const unsigned*)&A[g * 88 + k0];
        af[1] = *(const unsigned*)&A[(g + 8) * 88 + k0];
        af[2] = *(const unsigned*)&A[g * 88 + k0 + 8];
        af[3] = *(const unsigned*)&A[(g + 8) * 88 + k0 + 8];
#pragma unroll
        for (int nt = 0; nt < 4; nt++) {
            int nn = 32 * w + 8 * nt + g;
            unsigned bf[2];
            bf[0] = __ldg((const unsigned*)&g_wT1[nn * 88 + k0]);
            bf[1] = __ldg((const unsigned*)&g_wT1[nn * 88 + k0 + 8]);
            mma16816(acc[nt], af, bf);
        }
    }

    bool rside = (n < 5000);
#pragma unroll
    for (int nt = 0; nt < 4; nt++) {
        int j = 32 * w + 8 * nt + 2 * tig;         // output cols j, j+1
        float2 bb = *(const float2*)&bias[j];
#pragma unroll
        for (int h = 0; h < 2; h++) {
            int b = 16 * h0 + g + 8 * h;
            float v0 = sigf(acc[nt][2 * h]     + bb.x);
            float v1 = sigf(acc[nt][2 * h + 1] + bb.y);
            if (rside) {
                int t = 2 * n + (j >> 6);
                size_t off = (size_t)t * SROW + b * 64 + (j & 63);
                float2 s = __half22float2(*(const __half2*)&g_XSh[off]);
                *(__half2*)&g_XS2h[off] = __floats2half2_rn(v0 * s.x, v1 * s.y);
            } else {
                size_t off = (size_t)b * S_STRIDE + (n - 5000) * 128 + j;
                __half2 hv = __floats2half2_rn(v0, v1);
                __stcs((unsigned*)&g_Uh[off], *(unsigned*)&hv);
            }
        }
    }
}

// ---------------- pass 2: SpMM + GEMM2 + relu + GRU combine -> out ----------------
__global__ void __launch_bounds__(128, 8) k_spmm2f(const float* __restrict__ bias,
                                                   const float* __restrict__ state,
                                                   float* __restrict__ out) {
    __shared__ int    scol[128];
    __shared__ float  sval[128];
    __shared__ __half A[16 * 88];
    int n = blockIdx.x >> 1;
    int h0 = blockIdx.x & 1;
    int tid = threadIdx.x;
    int slot = (h0 << 7) + tid;
    float a[8] = {0.f, 0.f, 0.f, 0.f, 0.f, 0.f, 0.f, 0.f};
    gather_row((const uint4*)g_XS2h, n, slot, tid, scol, sval, a);
    stage_A(A, n, slot, a);
    __syncthreads();

    int lane = tid & 31, w = tid >> 5;
    int g = lane >> 2, tig = lane & 3;
    float acc[2][4] = {};
#pragma unroll
    for (int ks = 0; ks < 5; ks++) {
        int k0 = ks * 16 + 2 * tig;
        unsigned af[4];
        af[0] = *(const unsigned*)&A[g * 88 + k0];
        af[1] = *(const unsigned*)&A[(g + 8) * 88 + k0];
        af[2] = *(const unsigned*)&A[g * 88 + k0 + 8];
        af[3] = *(const unsigned*)&A[(g + 8) * 88 + k0 + 8];
#pragma unroll
        for (int nt = 0; nt < 2; nt++) {
            int nn = 16 * w + 8 * nt + g;
            unsigned bf[2];
            bf[0] = __ldg((const unsigned*)&g_wT2[nn * 88 + k0]);
            bf[1] = __ldg((const unsigned*)&g_wT2[nn * 88 + k0 + 8]);
            mma16816(acc[nt], af, bf);
        }
    }

#pragma unroll
    for (int nt = 0; nt < 2; nt++) {
        int j = 16 * w + 8 * nt + 2 * tig;         // cols j, j+1 (0..63)
        float2 bb = *(const float2*)&bias[j];
#pragma unroll
        for (int h = 0; h < 2; h++) {
            int b = 16 * h0 + g + 8 * h;
            float c0 = fmaxf(acc[nt][2 * h]     + bb.x, 0.0f);
            float c1 = fmaxf(acc[nt][2 * h + 1] + bb.y, 0.0f);
            size_t off = (size_t)b * S_STRIDE + n * 64 + j;
            unsigned uu = __ldcs((const unsigned*)&g_Uh[off]);
            float2 u = __half22float2(*(__half2*)&uu);
            float2 s = *(const float2*)&state[off];
            float2 o;
            o.x = u.x * s.x + (1.0f - u.x) * c0;
            o.y = u.y * s.y + (1.0f - u.y) * c1;
            *(float2*)&out[off] = o;
        }
    }
}

// ---------------- launch ----------------
extern "C" void kernel_launch(void* const* d_in, const int* in_sizes, int n_in,
                              void* d_out, int out_size) {
    const float* inputs = (const float*)d_in[0];
    const float* state  = (const float*)d_in[1];
    const int*   m_rows = (const int*)d_in[2];
    const int*   m_cols = (const int*)d_in[3];
    const float* m_vals = (const float*)d_in[4];
    const float* w1     = (const float*)d_in[5];
    const float* b1     = (const float*)d_in[6];
    const float* w2     = (const float*)d_in[7];
    const float* b2     = (const float*)d_in[8];
    float* out = (float*)d_out;
    int nnz = in_sizes[2];

    // side: weight prep + builder, parallel with CSR chain
    cudaEventRecord(g_evFork, 0);
    cudaStreamWaitEvent(g_s1, g_evFork, 0);
    k_wprep<<<66, 256, 0, g_s1>>>(w1, w2);
    k_build<<<(XS_Q + N_NODES * NB + 255) / 256, 256, 0, g_s1>>>(inputs, state);

    // main: CSR chain
    k_zero<<<(N_NODES + 255) / 256, 256>>>();
    k_hist<<<(nnz + 255) / 256, 256>>>(m_rows, nnz);
    k_scan<<<1, 1024>>>();
    k_scatter<<<(nnz + 255) / 256, 256>>>(m_rows, m_cols, m_vals, nnz);
    cudaEventRecord(g_evCsr, 0);

    // side: inputs-part SpMM (needs CSR; build/wprep ordered before it on g_s1)
    cudaStreamWaitEvent(g_s1, g_evCsr, 0);
    k_spmm_in<<<(N_NODES * NB + 255) / 256, 256, 0, g_s1>>>();
    cudaEventRecord(g_evIn, g_s1);

    // main: fused passes (evIn implies wprep+build+CSR+YI all complete)
    cudaStreamWaitEvent(0, g_evIn, 0);
    k_spmm1f<<<2 * N_NODES, 128>>>(b1);                 // XSh -> (XS2h, Uh)
    k_spmm2f<<<2 * N_NODES, 128>>>(b2, state, out);     // XS2h -> out
}